// round 2
// baseline (speedup 1.0000x reference)
#include <cuda_runtime.h>

namespace {
constexpr int kB = 16, kH = 256, kC = 128, kW = 128;
}

// Scratch (device globals: allocation-free contract).
// g_q/g_k/g_v: (B, W, H, C).  g_q is reused as m5 (B,W,C,H) after pass 2,
// g_k reused as m6 (B,H,C,W) after pass 5 (both dead by then).
__device__ float g_q[(size_t)kB * kW * kH * kC];
__device__ float g_k[(size_t)kB * kW * kH * kC];
__device__ float g_v[(size_t)kB * kW * kH * kC];
__device__ float g_s[(size_t)kB * kW * kC * kC];   // scores/attn (B,W,D,C)
__device__ float g_wn[(size_t)kB * kW * kC * kC];  // wn (B,W,E,C)

// Generic batched GEMM:  C[m,n] = alpha * sum_k A[k,m] * B[k,n] + bias_m[m] + bias_n[n]
// Per-batch operand offsets: (z/div)*so + (z%div)*si.
// A addressed as A[k*sAk + m*sAm] (AKC=true means sAk==1 path, else sAm==1).
// B addressed as B[k*sBk + n]  (n always unit stride).
// C addressed as C[m + n*sCn]  (m always unit stride).
// Tile: 128(M) x 128(N) x 8(K), 256 threads, 8x8 microtile. No bounds checks
// (all dims are exact multiples).
template <bool AKC>
__global__ __launch_bounds__(256) void gemm_bt(
    const float* __restrict__ A, int a_div, long a_so, long a_si, int sAk, int sAm,
    const float* __restrict__ Bp, int b_div, long b_so, long b_si, int sBk,
    float* __restrict__ Cp, int c_div, long c_so, long c_si, int sCn,
    const float* __restrict__ bias_m, const float* __restrict__ bias_n,
    float alpha, int K)
{
  constexpr int BK = 8;
  __shared__ float As[BK][132];
  __shared__ float Bs[BK][132];
  const int tid = threadIdx.x;
  const int z = blockIdx.z;
  const int bx = blockIdx.x, by = blockIdx.y;

  A  += (long)(z / a_div) * a_so + (long)(z % a_div) * a_si + (long)bx * 128 * sAm;
  Bp += (long)(z / b_div) * b_so + (long)(z % b_div) * b_si + (long)by * 128;
  Cp += (long)(z / c_div) * c_so + (long)(z % c_div) * c_si
        + (long)bx * 128 + (long)by * 128 * sCn;

  const int tx = tid & 15, ty = tid >> 4;
  float acc[8][8] = {};

  for (int k0 = 0; k0 < K; k0 += BK) {
    if (!AKC) {
      // m is unit stride: coalesced float4 along m
      int kk = tid >> 5, mm = (tid & 31) * 4;
      *reinterpret_cast<float4*>(&As[kk][mm]) =
          *reinterpret_cast<const float4*>(A + (long)(k0 + kk) * sAk + mm);
    } else {
      // k is unit stride: coalesced float4 along k, transpose into smem
      int mm = tid >> 1, kv = (tid & 1) * 4;
      float4 va = *reinterpret_cast<const float4*>(A + (long)mm * sAm + k0 + kv);
      As[kv + 0][mm] = va.x; As[kv + 1][mm] = va.y;
      As[kv + 2][mm] = va.z; As[kv + 3][mm] = va.w;
    }
    {
      int kk = tid >> 5, nn = (tid & 31) * 4;
      *reinterpret_cast<float4*>(&Bs[kk][nn]) =
          *reinterpret_cast<const float4*>(Bp + (long)(k0 + kk) * sBk + nn);
    }
    __syncthreads();
#pragma unroll
    for (int kk = 0; kk < BK; kk++) {
      float4 a0 = *reinterpret_cast<const float4*>(&As[kk][tx * 8]);
      float4 a1 = *reinterpret_cast<const float4*>(&As[kk][tx * 8 + 4]);
      float4 b0 = *reinterpret_cast<const float4*>(&Bs[kk][ty * 8]);
      float4 b1 = *reinterpret_cast<const float4*>(&Bs[kk][ty * 8 + 4]);
      float av[8] = {a0.x, a0.y, a0.z, a0.w, a1.x, a1.y, a1.z, a1.w};
      float bv[8] = {b0.x, b0.y, b0.z, b0.w, b1.x, b1.y, b1.z, b1.w};
#pragma unroll
      for (int i = 0; i < 8; i++)
#pragma unroll
        for (int j = 0; j < 8; j++) acc[i][j] += av[i] * bv[j];
    }
    __syncthreads();
  }

  float bm[8];
#pragma unroll
  for (int i = 0; i < 8; i++)
    bm[i] = bias_m ? bias_m[bx * 128 + tx * 8 + i] : 0.f;
#pragma unroll
  for (int j = 0; j < 8; j++) {
    float bnj = bias_n ? bias_n[by * 128 + ty * 8 + j] : 0.f;
    long nof = (long)(ty * 8 + j) * sCn;
    float4 v0, v1;
    v0.x = alpha * acc[0][j] + bm[0] + bnj;
    v0.y = alpha * acc[1][j] + bm[1] + bnj;
    v0.z = alpha * acc[2][j] + bm[2] + bnj;
    v0.w = alpha * acc[3][j] + bm[3] + bnj;
    v1.x = alpha * acc[4][j] + bm[4] + bnj;
    v1.y = alpha * acc[5][j] + bm[5] + bnj;
    v1.z = alpha * acc[6][j] + bm[6] + bnj;
    v1.w = alpha * acc[7][j] + bm[7] + bnj;
    *reinterpret_cast<float4*>(Cp + nof + tx * 8) = v0;
    *reinterpret_cast<float4*>(Cp + nof + tx * 8 + 4) = v1;
  }
}

// Softmax over the w axis of scores stored as (B, W, D, C).
// One thread per (b, d, c); stride between consecutive w is C*C.
// Coalesced: consecutive threads -> consecutive c.
__global__ __launch_bounds__(256) void softmax_w(float* __restrict__ s)
{
  long t = (long)blockIdx.x * blockDim.x + threadIdx.x;  // < B*C*C
  int b = (int)(t / (kC * kC));
  int r = (int)(t % (kC * kC));
  float* p = s + (long)b * kW * kC * kC + r;
  const long st = (long)kC * kC;
  float mx = -1e30f;
  for (int w = 0; w < kW; w++) mx = fmaxf(mx, p[w * st]);
  float sum = 0.f;
  for (int w = 0; w < kW; w++) {
    float e = __expf(p[w * st] - mx);
    sum += e;
    p[w * st] = e;
  }
  float inv = 1.f / sum;
  for (int w = 0; w < kW; w++) p[w * st] *= inv;
}

// Transpose m5 (B,W,C,H) -> m6 (B,H,C,W): for each (b,c), transpose the
// (w,h) matrix. 32x32 smem tiles, coalesced both sides.
__global__ __launch_bounds__(256) void trans_wh(const float* __restrict__ in,
                                                float* __restrict__ out)
{
  __shared__ float tile[32][33];
  int bc = blockIdx.z;
  int b = bc / kC, c = bc % kC;
  long ibase = (long)b * kW * kC * kH + (long)c * kH;   // + w*C*H + h
  long obase = (long)b * kH * kC * kW + (long)c * kW;   // + h*C*W + w
  int w0 = blockIdx.x * 32, h0 = blockIdx.y * 32;
  int txl = threadIdx.x;
#pragma unroll
  for (int i = threadIdx.y; i < 32; i += 8)
    tile[i][txl] = in[ibase + (long)(w0 + i) * (kC * kH) + h0 + txl];
  __syncthreads();
#pragma unroll
  for (int i = threadIdx.y; i < 32; i += 8)
    out[obase + (long)(h0 + i) * (kC * kW) + w0 + txl] = tile[txl][i];
}

extern "C" void kernel_launch(void* const* d_in, const int* in_sizes, int n_in,
                              void* d_out, int out_size)
{
  (void)in_sizes; (void)n_in; (void)out_size;
  const float* x  = (const float*)d_in[0];
  const float* Wq = (const float*)d_in[1];
  const float* bq = (const float*)d_in[2];
  const float* Wk = (const float*)d_in[3];
  const float* bk = (const float*)d_in[4];
  const float* Wv = (const float*)d_in[5];
  const float* bv = (const float*)d_in[6];
  const float* Wn = (const float*)d_in[7];
  const float* bn = (const float*)d_in[8];
  const float* Wo = (const float*)d_in[9];
  const float* bo = (const float*)d_in[10];
  float* out = (float*)d_out;

  float *q, *k, *v, *s, *wn;
  cudaGetSymbolAddress((void**)&q, g_q);
  cudaGetSymbolAddress((void**)&k, g_k);
  cudaGetSymbolAddress((void**)&v, g_v);
  cudaGetSymbolAddress((void**)&s, g_s);
  cudaGetSymbolAddress((void**)&wn, g_wn);

  const long HC = (long)kH * kC;   // 32768
  const long CW = (long)kC * kW;   // 16384
  const long CC = (long)kC * kC;   // 16384
  const long CH = (long)kC * kH;   // 32768

  // Pass 1: Q/K/V projections. z=(b*H+h). A=W?[c,d] (k=c,m=d), B=x[b,h,c,w]
  // (k=c,n=w). Out (B,W,H,C): off=(z/H)*W*H*C+(z%H)*C, C[m + n*H*C].
  {
    dim3 g(1, 1, kB * kH);
    gemm_bt<false><<<g, 256>>>(Wq, 1, 0, 0, kC, 1,
                               x, 1, CW, 0, kW,
                               q, kH, (long)kW * HC, kC, (int)HC,
                               bq, nullptr, 1.f, kC);
    gemm_bt<false><<<g, 256>>>(Wk, 1, 0, 0, kC, 1,
                               x, 1, CW, 0, kW,
                               k, kH, (long)kW * HC, kC, (int)HC,
                               bk, nullptr, 1.f, kC);
    gemm_bt<false><<<g, 256>>>(Wv, 1, 0, 0, kC, 1,
                               x, 1, CW, 0, kW,
                               v, kH, (long)kW * HC, kC, (int)HC,
                               bv, nullptr, 1.f, kC);
  }

  // Pass 2: scores[b,w][c,d] = sum_h q[h,c]*k[h,d] / sqrt(W). z=(b*W+w).
  // Out s stored (B,W,D,C): C[m=c + n=d*C].
  gemm_bt<false><<<dim3(1, 1, kB * kW), 256>>>(
      q, 1, HC, 0, kC, 1,
      k, 1, HC, 0, kC,
      s, 1, CC, 0, kC,
      nullptr, nullptr, 0.08838834764831845f, kH);

  // Pass 3: softmax over w (in place).
  softmax_w<<<(kB * kC * kC) / 256, 256>>>(s);

  // Pass 4: wn[b,w][c,e] = sum_d attn[d,c]*Wn[d,e] + bn[e].
  // Out stored (B,W,E,C): C[m=c + n=e*C].
  gemm_bt<false><<<dim3(1, 1, kB * kW), 256>>>(
      s, 1, CC, 0, kC, 1,
      Wn, 1, 0, 0, kC,
      wn, 1, CC, 0, kC,
      nullptr, bn, 1.f, kC);

  // Pass 5: m[b,w][h,c] = sum_e v[h,e]*wn[e,c]. A=v (k=e unit stride -> AKC).
  // Out m5 (B,W,C,H) into g_q: C[m=h + n=c*H]. M=256 -> grid.x=2.
  gemm_bt<true><<<dim3(2, 1, kB * kW), 256>>>(
      v, 1, HC, 0, 1, kC,
      wn, 1, CC, 0, kC,
      q, 1, CH, 0, kH,
      nullptr, nullptr, 1.f, kC);

  // Pass 5.5: transpose m5 (B,W,C,H) -> m6 (B,H,C,W) into g_k.
  trans_wh<<<dim3(kW / 32, kH / 32, kB * kC), dim3(32, 8)>>>(q, k);

  // Pass 6: out[b,h][w,o] = sum_c m6[c,w]*Wo[c,o] + bo[o]. z=(b*H+h).
  // Out (B,H,C,W): C[m=w + n=o*W].
  gemm_bt<false><<<dim3(1, 1, kB * kH), 256>>>(
      k, 1, CW, 0, kW, 1,
      Wo, 1, 0, 0, kC,
      out, 1, CW, 0, kW,
      nullptr, bo, 1.f, kC);
}

// round 4
// speedup vs baseline: 2.2303x; 2.2303x over previous
#include <cuda_runtime.h>
#include <cstdint>

namespace {
constexpr int kB = 16, kH = 256, kC = 128, kW = 128;
}

// Scratch (device globals: allocation-free contract).
__device__ float g_q[(size_t)kB * kW * kH * kC];   // q (B,W,H,C); reused as m5 (B,W,C,H)
__device__ float g_k[(size_t)kB * kW * kH * kC];   // k (B,W,H,C); reused as m6 (B,H,C,W)
__device__ float g_v[(size_t)kB * kW * kH * kC];   // v (B,W,H,C)
__device__ float g_s[(size_t)kB * kW * kC * kC];   // scores/attn (B,W,D,C)
__device__ float g_wn[(size_t)kB * kW * kC * kC];  // wn (B,W,E,C)

__device__ __forceinline__ uint32_t f2tf32(float f) {
  uint32_t r;
  asm("cvt.rna.tf32.f32 %0, %1;" : "=r"(r) : "f"(f));
  return r;
}

// SMEM row stride (words). 36 => fragment-load banks (4q+t)%32: conflict-free.
constexpr int kLds = 36;

// Load 16 k-elements of one row into smem (tf32-rounded).
// KC=true: k unit stride in global (float4 loads). Else stride sK, unit row.
template <bool KC>
__device__ __forceinline__ void load_row16(uint32_t* __restrict__ dst,
                                           const float* __restrict__ src, long sK) {
  if (KC) {
#pragma unroll
    for (int i = 0; i < 4; i++) {
      float4 v = *reinterpret_cast<const float4*>(src + i * 4);
      dst[i * 4 + 0] = f2tf32(v.x);
      dst[i * 4 + 1] = f2tf32(v.y);
      dst[i * 4 + 2] = f2tf32(v.z);
      dst[i * 4 + 3] = f2tf32(v.w);
    }
  } else {
#pragma unroll
    for (int i = 0; i < 16; i++) dst[i] = f2tf32(src[(long)i * sK]);
  }
}

// Batched GEMM via mma.sync tf32 (fp32 accumulate):
//   C[m,n] = alpha * sum_k A[m*sAm + k*sAk] * B[n*sBn + k*sBk] + bias_m[m] + bias_n[n]
// Per-batch operand offsets: (z/div)*so + (z%div)*si. C[m + n*sCn], m unit stride.
// Tile 128(M) x 128(N), K in chunks of 32. 256 threads = 8 warps (2m x 4n),
// each warp 64x32 via 4x4 grid of m16n8k8.
template <bool AKC, bool BKC>
__global__ __launch_bounds__(256) void gemm_mma(
    const float* __restrict__ A, int a_div, long a_so, long a_si, long sAm, long sAk,
    const float* __restrict__ Bp, int b_div, long b_so, long b_si, long sBn, long sBk,
    float* __restrict__ Cp, int c_div, long c_so, long c_si, long sCn,
    const float* __restrict__ bias_m, const float* __restrict__ bias_n,
    float alpha, int K) {
  __shared__ uint32_t As[128 * kLds];
  __shared__ uint32_t Bs[128 * kLds];
  __shared__ float bmS[128], bnS[128];

  const int tid = threadIdx.x;
  const int lane = tid & 31, wid = tid >> 5;
  const int wm = (wid & 1) * 64, wn = (wid >> 1) * 32;
  const int z = blockIdx.z, bx = blockIdx.x, by = blockIdx.y;

  A += (long)(z / a_div) * a_so + (long)(z % a_div) * a_si + (long)bx * 128 * sAm;
  Bp += (long)(z / b_div) * b_so + (long)(z % b_div) * b_si + (long)by * 128 * sBn;
  Cp += (long)(z / c_div) * c_so + (long)(z % c_div) * c_si + (long)bx * 128 +
        (long)by * 128 * sCn;

  if (tid < 128) {
    bmS[tid] = bias_m ? bias_m[bx * 128 + tid] : 0.f;
    bnS[tid] = bias_n ? bias_n[by * 128 + tid] : 0.f;
  }

  float acc[4][4][4];
#pragma unroll
  for (int i = 0; i < 4; i++)
#pragma unroll
    for (int j = 0; j < 4; j++)
#pragma unroll
      for (int c = 0; c < 4; c++) acc[i][j][c] = 0.f;

  const int row = tid >> 1;          // smem row this thread fills
  const int khalf = (tid & 1) * 16;  // which 16-k half

  for (int k0 = 0; k0 < K; k0 += 32) {
    load_row16<AKC>(&As[row * kLds + khalf], A + (long)row * sAm + (long)(k0 + khalf) * sAk,
                    sAk);
    load_row16<BKC>(&Bs[row * kLds + khalf], Bp + (long)row * sBn + (long)(k0 + khalf) * sBk,
                    sBk);
    __syncthreads();

#pragma unroll
    for (int ks = 0; ks < 4; ks++) {
      const int kb = ks * 8 + (lane & 3);
      uint32_t af[4][4], bf[4][2];
#pragma unroll
      for (int im = 0; im < 4; im++) {
        int r0 = wm + im * 16 + (lane >> 2);
        af[im][0] = As[r0 * kLds + kb];
        af[im][1] = As[(r0 + 8) * kLds + kb];
        af[im][2] = As[r0 * kLds + kb + 4];
        af[im][3] = As[(r0 + 8) * kLds + kb + 4];
      }
#pragma unroll
      for (int in = 0; in < 4; in++) {
        int n0 = wn + in * 8 + (lane >> 2);
        bf[in][0] = Bs[n0 * kLds + kb];
        bf[in][1] = Bs[n0 * kLds + kb + 4];
      }
#pragma unroll
      for (int im = 0; im < 4; im++)
#pragma unroll
        for (int in = 0; in < 4; in++) {
          asm volatile(
              "mma.sync.aligned.m16n8k8.row.col.f32.tf32.tf32.f32 "
              "{%0,%1,%2,%3}, {%4,%5,%6,%7}, {%8,%9}, {%0,%1,%2,%3};"
              : "+f"(acc[im][in][0]), "+f"(acc[im][in][1]), "+f"(acc[im][in][2]),
                "+f"(acc[im][in][3])
              : "r"(af[im][0]), "r"(af[im][1]), "r"(af[im][2]), "r"(af[im][3]),
                "r"(bf[in][0]), "r"(bf[in][1]));
        }
    }
    __syncthreads();
  }

  // Epilogue. Fragment c: c0(row=g,col=2t) c1(g,2t+1) c2(g+8,2t) c3(g+8,2t+1).
  const int g = lane >> 2, t2 = (lane & 3) * 2;
#pragma unroll
  for (int im = 0; im < 4; im++) {
    int m0 = wm + im * 16 + g;
    int m1 = m0 + 8;
    float bm0 = bmS[m0], bm1 = bmS[m1];
#pragma unroll
    for (int in = 0; in < 4; in++) {
      int n0 = wn + in * 8 + t2;
      int n1 = n0 + 1;
      float bn0 = bnS[n0], bn1 = bnS[n1];
      Cp[(long)n0 * sCn + m0] = alpha * acc[im][in][0] + bm0 + bn0;
      Cp[(long)n1 * sCn + m0] = alpha * acc[im][in][1] + bm0 + bn1;
      Cp[(long)n0 * sCn + m1] = alpha * acc[im][in][2] + bm1 + bn0;
      Cp[(long)n1 * sCn + m1] = alpha * acc[im][in][3] + bm1 + bn1;
    }
  }
}

// Softmax over the w axis of scores stored as (B, W, D, C).
__global__ __launch_bounds__(256) void softmax_w(float* __restrict__ s) {
  long t = (long)blockIdx.x * blockDim.x + threadIdx.x;  // < B*C*C
  int b = (int)(t / (kC * kC));
  int r = (int)(t % (kC * kC));
  float* p = s + (long)b * kW * kC * kC + r;
  const long st = (long)kC * kC;
  float mx = -1e30f;
  for (int w = 0; w < kW; w++) mx = fmaxf(mx, p[w * st]);
  float sum = 0.f;
  for (int w = 0; w < kW; w++) {
    float e = __expf(p[w * st] - mx);
    sum += e;
    p[w * st] = e;
  }
  float inv = 1.f / sum;
  for (int w = 0; w < kW; w++) p[w * st] *= inv;
}

// Transpose m5 (B,W,C,H) -> m6 (B,H,C,W).
__global__ __launch_bounds__(256) void trans_wh(const float* __restrict__ in,
                                                float* __restrict__ out) {
  __shared__ float tile[32][33];
  int bc = blockIdx.z;
  int b = bc / kC, c = bc % kC;
  long ibase = (long)b * kW * kC * kH + (long)c * kH;
  long obase = (long)b * kH * kC * kW + (long)c * kW;
  int w0 = blockIdx.x * 32, h0 = blockIdx.y * 32;
  int txl = threadIdx.x;
#pragma unroll
  for (int i = threadIdx.y; i < 32; i += 8)
    tile[i][txl] = in[ibase + (long)(w0 + i) * (kC * kH) + h0 + txl];
  __syncthreads();
#pragma unroll
  for (int i = threadIdx.y; i < 32; i += 8)
    out[obase + (long)(h0 + i) * (kC * kW) + w0 + txl] = tile[txl][i];
}

extern "C" void kernel_launch(void* const* d_in, const int* in_sizes, int n_in,
                              void* d_out, int out_size) {
  (void)in_sizes; (void)n_in; (void)out_size;
  const float* x  = (const float*)d_in[0];
  const float* Wq = (const float*)d_in[1];
  const float* bq = (const float*)d_in[2];
  const float* Wk = (const float*)d_in[3];
  const float* bk = (const float*)d_in[4];
  const float* Wv = (const float*)d_in[5];
  const float* bv = (const float*)d_in[6];
  const float* Wn = (const float*)d_in[7];
  const float* bn = (const float*)d_in[8];
  const float* Wo = (const float*)d_in[9];
  const float* bo = (const float*)d_in[10];
  float* out = (float*)d_out;

  float *q, *k, *v, *s, *wn;
  cudaGetSymbolAddress((void**)&q, g_q);
  cudaGetSymbolAddress((void**)&k, g_k);
  cudaGetSymbolAddress((void**)&v, g_v);
  cudaGetSymbolAddress((void**)&s, g_s);
  cudaGetSymbolAddress((void**)&wn, g_wn);

  const long HC = (long)kH * kC;
  const long CW = (long)kC * kW;
  const long CC = (long)kC * kC;
  const long CH = (long)kC * kH;

  // Pass 1: Q/K/V projections. z=(b*H+h). m=d, n=w, k=c.
  {
    dim3 g(1, 1, kB * kH);
    gemm_mma<false, false><<<g, 256>>>(Wq, 1, 0, 0, 1, kC,
                                       x, 1, CW, 0, 1, kW,
                                       q, kH, (long)kW * HC, kC, HC,
                                       bq, nullptr, 1.f, kC);
    gemm_mma<false, false><<<g, 256>>>(Wk, 1, 0, 0, 1, kC,
                                       x, 1, CW, 0, 1, kW,
                                       k, kH, (long)kW * HC, kC, HC,
                                       bk, nullptr, 1.f, kC);
    gemm_mma<false, false><<<g, 256>>>(Wv, 1, 0, 0, 1, kC,
                                       x, 1, CW, 0, 1, kW,
                                       v, kH, (long)kW * HC, kC, HC,
                                       bv, nullptr, 1.f, kC);
  }

  // Pass 2: scores[b,w][c,d] = sum_h q*k / sqrt(W). z=(b*W+w). m=c, n=d, k=h.
  gemm_mma<false, false><<<dim3(1, 1, kB * kW), 256>>>(
      q, 1, HC, 0, 1, kC,
      k, 1, HC, 0, 1, kC,
      s, 1, CC, 0, kC,
      nullptr, nullptr, 0.08838834764831845f, kH);

  // Pass 3: softmax over w (in place).
  softmax_w<<<(kB * kC * kC) / 256, 256>>>(s);

  // Pass 4: wn[b,w][c,e] = sum_d attn[d,c]*Wn[d,e] + bn[e]. m=c, n=e, k=d.
  gemm_mma<false, false><<<dim3(1, 1, kB * kW), 256>>>(
      s, 1, CC, 0, 1, kC,
      Wn, 1, 0, 0, 1, kC,
      wn, 1, CC, 0, kC,
      nullptr, bn, 1.f, kC);

  // Pass 5: m[b,w][h,c] = sum_e v[h,e]*wn[e,c]. m=h (256 -> grid.x=2), n=c, k=e.
  gemm_mma<true, false><<<dim3(2, 1, kB * kW), 256>>>(
      v, 1, HC, 0, kC, 1,
      wn, 1, CC, 0, 1, kC,
      q, 1, CH, 0, kH,
      nullptr, nullptr, 1.f, kC);

  // Pass 5.5: transpose m5 (B,W,C,H) -> m6 (B,H,C,W).
  trans_wh<<<dim3(kW / 32, kH / 32, kB * kC), dim3(32, 8)>>>(q, k);

  // Pass 6: out[b,h][w,o] = sum_c m6[c,w]*Wo[c,o] + bo[o]. m=w, n=o, k=c.
  gemm_mma<false, false><<<dim3(1, 1, kB * kH), 256>>>(
      k, 1, CW, 0, 1, kW,
      Wo, 1, 0, 0, 1, kC,
      out, 1, CW, 0, kW,
      nullptr, bo, 1.f, kC);
}

// round 5
// speedup vs baseline: 2.2870x; 1.0254x over previous
#include <cuda_runtime.h>
#include <cstdint>

namespace {
constexpr int kB = 16, kH = 256, kC = 128, kW = 128;
constexpr long kCC = (long)kC * kC;
}

// Scratch (device globals: allocation-free contract).
__device__ float g_q[(size_t)kB * kW * kH * kC];   // q (B,W,H,C); reused as m5 (B,W,C,H)
__device__ float g_k[(size_t)kB * kW * kH * kC];   // k (B,W,H,C); reused as m6 (B,H,C,W)
__device__ float g_v[(size_t)kB * kW * kH * kC];   // v (B,W,H,C)
__device__ float g_s[(size_t)kB * kW * kC * kC];   // exp(scores) (B,W,D,C)
__device__ float g_wn[(size_t)kB * kW * kC * kC];  // wn (B,W,E,C)
__device__ float g_inv[(size_t)kB * kC * kC];      // 1/sum_w exp (B,D,C)

__device__ __forceinline__ uint32_t f2tf32(float f) {
  uint32_t r;
  asm("cvt.rna.tf32.f32 %0, %1;" : "=r"(r) : "f"(f));
  return r;
}

// exp on the FMA pipe (no MUFU): exp(x) = 2^r * e^f, deg-5 Taylor on |f|<=ln2/2.
__device__ __forceinline__ float fast_exp(float x) {
  x = fminf(fmaxf(x, -30.f), 30.f);
  float r = rintf(x * 1.44269504f);
  float f = fmaf(r, -0.6931471805599453f, x);
  float p = 1.f + f * (1.f + f * (0.5f + f * (0.16666667f +
                f * (0.041666667f + f * 0.0083333333f))));
  return p * __int_as_float(((int)r + 127) << 23);
}

// SMEM row stride (words). 36 => fragment-load banks (4q+t)%32: conflict-free.
constexpr int kLds = 36;

// Load 16 k-elements of one row into smem (tf32-rounded). KC=true: k unit
// stride (float4). NORM: multiply by nsrc at identical offsets (AKC=false only).
template <bool KC, bool NORM>
__device__ __forceinline__ void load_row16(uint32_t* __restrict__ dst,
                                           const float* __restrict__ src, long sK,
                                           const float* __restrict__ nsrc) {
  if (KC) {
#pragma unroll
    for (int i = 0; i < 4; i++) {
      float4 v = *reinterpret_cast<const float4*>(src + i * 4);
      dst[i * 4 + 0] = f2tf32(v.x);
      dst[i * 4 + 1] = f2tf32(v.y);
      dst[i * 4 + 2] = f2tf32(v.z);
      dst[i * 4 + 3] = f2tf32(v.w);
    }
  } else {
#pragma unroll
    for (int i = 0; i < 16; i++) {
      float v = src[(long)i * sK];
      if (NORM) v *= nsrc[(long)i * sK];
      dst[i] = f2tf32(v);
    }
  }
}

// Core 128x128 GEMM body via mma.sync tf32 (fp32 accumulate).
//   C[m,n] = alpha * sum_k A[m*sAm+k*sAk] * B[n*sBn+k*sBk] (+biases) ; C[m + n*sCn]
// EEPI: epilogue writes fast_exp(alpha*acc) (no bias). ANORM: A *= nrm on load.
template <bool AKC, bool BKC, bool ANORM, bool EEPI>
__device__ __forceinline__ void gemm_body(
    const float* __restrict__ A, long sAm, long sAk,
    const float* __restrict__ Bp, long sBn, long sBk,
    float* __restrict__ Cp, long sCn,
    const float* __restrict__ nrm,
    const float* __restrict__ bias_m, const float* __restrict__ bias_n,
    float alpha, int K) {
  __shared__ uint32_t As[128 * kLds];
  __shared__ uint32_t Bs[128 * kLds];
  __shared__ float bmS[128], bnS[128];

  const int tid = threadIdx.x;
  const int lane = tid & 31, wid = tid >> 5;
  const int wm = (wid & 1) * 64, wn = (wid >> 1) * 32;

  if (!EEPI && tid < 128) {
    bmS[tid] = bias_m ? bias_m[tid] : 0.f;
    bnS[tid] = bias_n ? bias_n[tid] : 0.f;
  }

  float acc[4][4][4];
#pragma unroll
  for (int i = 0; i < 4; i++)
#pragma unroll
    for (int j = 0; j < 4; j++)
#pragma unroll
      for (int c = 0; c < 4; c++) acc[i][j][c] = 0.f;

  const int row = tid >> 1;
  const int khalf = (tid & 1) * 16;

  for (int k0 = 0; k0 < K; k0 += 32) {
    const long aoff = (long)row * sAm + (long)(k0 + khalf) * sAk;
    load_row16<AKC, ANORM>(&As[row * kLds + khalf], A + aoff, sAk,
                           ANORM ? nrm + aoff : nullptr);
    load_row16<BKC, false>(&Bs[row * kLds + khalf],
                           Bp + (long)row * sBn + (long)(k0 + khalf) * sBk, sBk, nullptr);
    __syncthreads();

#pragma unroll
    for (int ks = 0; ks < 4; ks++) {
      const int kb = ks * 8 + (lane & 3);
      uint32_t af[4][4], bf[4][2];
#pragma unroll
      for (int im = 0; im < 4; im++) {
        int r0 = wm + im * 16 + (lane >> 2);
        af[im][0] = As[r0 * kLds + kb];
        af[im][1] = As[(r0 + 8) * kLds + kb];
        af[im][2] = As[r0 * kLds + kb + 4];
        af[im][3] = As[(r0 + 8) * kLds + kb + 4];
      }
#pragma unroll
      for (int in = 0; in < 4; in++) {
        int n0 = wn + in * 8 + (lane >> 2);
        bf[in][0] = Bs[n0 * kLds + kb];
        bf[in][1] = Bs[n0 * kLds + kb + 4];
      }
#pragma unroll
      for (int im = 0; im < 4; im++)
#pragma unroll
        for (int in = 0; in < 4; in++) {
          asm volatile(
              "mma.sync.aligned.m16n8k8.row.col.f32.tf32.tf32.f32 "
              "{%0,%1,%2,%3}, {%4,%5,%6,%7}, {%8,%9}, {%0,%1,%2,%3};"
              : "+f"(acc[im][in][0]), "+f"(acc[im][in][1]), "+f"(acc[im][in][2]),
                "+f"(acc[im][in][3])
              : "r"(af[im][0]), "r"(af[im][1]), "r"(af[im][2]), "r"(af[im][3]),
                "r"(bf[in][0]), "r"(bf[in][1]));
        }
    }
    __syncthreads();
  }

  const int g = lane >> 2, t2 = (lane & 3) * 2;
#pragma unroll
  for (int im = 0; im < 4; im++) {
    int m0 = wm + im * 16 + g;
    int m1 = m0 + 8;
    float bm0 = EEPI ? 0.f : bmS[m0], bm1 = EEPI ? 0.f : bmS[m1];
#pragma unroll
    for (int in = 0; in < 4; in++) {
      int n0 = wn + in * 8 + t2;
      int n1 = n0 + 1;
      if (EEPI) {
        Cp[(long)n0 * sCn + m0] = fast_exp(alpha * acc[im][in][0]);
        Cp[(long)n1 * sCn + m0] = fast_exp(alpha * acc[im][in][1]);
        Cp[(long)n0 * sCn + m1] = fast_exp(alpha * acc[im][in][2]);
        Cp[(long)n1 * sCn + m1] = fast_exp(alpha * acc[im][in][3]);
      } else {
        float bn0 = bnS[n0], bn1 = bnS[n1];
        Cp[(long)n0 * sCn + m0] = alpha * acc[im][in][0] + bm0 + bn0;
        Cp[(long)n1 * sCn + m0] = alpha * acc[im][in][1] + bm0 + bn1;
        Cp[(long)n0 * sCn + m1] = alpha * acc[im][in][2] + bm1 + bn0;
        Cp[(long)n1 * sCn + m1] = alpha * acc[im][in][3] + bm1 + bn1;
      }
    }
  }
}

// Fused QKV: grid (1, 3, B*H); y selects weight/bias/output; x tile reused via L2.
__global__ __launch_bounds__(256) void gemm_qkv(
    const float* __restrict__ x,
    const float* __restrict__ Wq, const float* __restrict__ Wk, const float* __restrict__ Wv,
    const float* __restrict__ bq, const float* __restrict__ bk, const float* __restrict__ bv,
    float* __restrict__ q, float* __restrict__ k, float* __restrict__ v) {
  const int z = blockIdx.z, y = blockIdx.y;
  const float* A = (y == 0) ? Wq : (y == 1) ? Wk : Wv;
  const float* bm = (y == 0) ? bq : (y == 1) ? bk : bv;
  float* C = ((y == 0) ? q : (y == 1) ? k : v) +
             (long)(z / kH) * ((long)kW * kH * kC) + (long)(z % kH) * kC;
  const float* B = x + (long)z * kC * kW;
  gemm_body<false, false, false, false>(A, 1, kC, B, 1, kW, C, (long)kH * kC,
                                        nullptr, bm, nullptr, 1.f, kC);
}

template <bool AKC, bool BKC, bool ANORM, bool EEPI>
__global__ __launch_bounds__(256) void gemm_gen(
    const float* __restrict__ A, int a_div, long a_so, long a_si, long sAm, long sAk,
    const float* __restrict__ Bp, int b_div, long b_so, long b_si, long sBn, long sBk,
    float* __restrict__ Cp, int c_div, long c_so, long c_si, long sCn,
    const float* __restrict__ nrm_base, int nrm_div,
    const float* __restrict__ bias_m, const float* __restrict__ bias_n,
    float alpha, int K) {
  const int z = blockIdx.z, bx = blockIdx.x, by = blockIdx.y;
  A += (long)(z / a_div) * a_so + (long)(z % a_div) * a_si + (long)bx * 128 * sAm;
  Bp += (long)(z / b_div) * b_so + (long)(z % b_div) * b_si + (long)by * 128 * sBn;
  Cp += (long)(z / c_div) * c_so + (long)(z % c_div) * c_si + (long)bx * 128 +
        (long)by * 128 * sCn;
  const float* nrm = nullptr;
  if (ANORM) nrm = nrm_base + (long)(z / nrm_div) * kCC + (long)bx * 128 * sAm;
  gemm_body<AKC, BKC, ANORM, EEPI>(A, sAm, sAk, Bp, sBn, sBk, Cp, sCn, nrm,
                                   bias_m ? bias_m + bx * 128 : nullptr,
                                   bias_n ? bias_n + by * 128 : nullptr, alpha, K);
}

// Per-(b,d,c) reciprocal of sum over w of exp(scores) stored in s (B,W,D,C).
__global__ __launch_bounds__(256) void softmax_sum(const float* __restrict__ s,
                                                   float* __restrict__ inv) {
  long t = (long)blockIdx.x * blockDim.x + threadIdx.x;  // < B*C*C
  int b = (int)(t / kCC);
  int r = (int)(t % kCC);
  const float* p = s + (long)b * kW * kCC + r;
  float l = 0.f;
#pragma unroll 8
  for (int w = 0; w < kW; w++) l += p[(long)w * kCC];
  inv[t] = 1.f / l;
}

// Transpose m5 (B,W,C,H) -> m6 (B,H,C,W).
__global__ __launch_bounds__(256) void trans_wh(const float* __restrict__ in,
                                                float* __restrict__ out) {
  __shared__ float tile[32][33];
  int bc = blockIdx.z;
  int b = bc / kC, c = bc % kC;
  long ibase = (long)b * kW * kC * kH + (long)c * kH;
  long obase = (long)b * kH * kC * kW + (long)c * kW;
  int w0 = blockIdx.x * 32, h0 = blockIdx.y * 32;
  int txl = threadIdx.x;
#pragma unroll
  for (int i = threadIdx.y; i < 32; i += 8)
    tile[i][txl] = in[ibase + (long)(w0 + i) * (kC * kH) + h0 + txl];
  __syncthreads();
#pragma unroll
  for (int i = threadIdx.y; i < 32; i += 8)
    out[obase + (long)(h0 + i) * (kC * kW) + w0 + txl] = tile[txl][i];
}

extern "C" void kernel_launch(void* const* d_in, const int* in_sizes, int n_in,
                              void* d_out, int out_size) {
  (void)in_sizes; (void)n_in; (void)out_size;
  const float* x  = (const float*)d_in[0];
  const float* Wq = (const float*)d_in[1];
  const float* bq = (const float*)d_in[2];
  const float* Wk = (const float*)d_in[3];
  const float* bk = (const float*)d_in[4];
  const float* Wv = (const float*)d_in[5];
  const float* bv = (const float*)d_in[6];
  const float* Wn = (const float*)d_in[7];
  const float* bn = (const float*)d_in[8];
  const float* Wo = (const float*)d_in[9];
  const float* bo = (const float*)d_in[10];
  float* out = (float*)d_out;

  float *q, *k, *v, *s, *wn, *inv;
  cudaGetSymbolAddress((void**)&q, g_q);
  cudaGetSymbolAddress((void**)&k, g_k);
  cudaGetSymbolAddress((void**)&v, g_v);
  cudaGetSymbolAddress((void**)&s, g_s);
  cudaGetSymbolAddress((void**)&wn, g_wn);
  cudaGetSymbolAddress((void**)&inv, g_inv);

  const long HC = (long)kH * kC;
  const long CW = (long)kC * kW;
  const long CC = kCC;
  const long CH = (long)kC * kH;

  // Pass 1: fused Q/K/V projections. z=(b*H+h), y selects head. m=d, n=w, k=c.
  gemm_qkv<<<dim3(1, 3, kB * kH), 256>>>(x, Wq, Wk, Wv, bq, bk, bv, q, k, v);

  // Pass 2: s[b,w][c,d] = exp(sum_h q*k / sqrt(W)). z=(b*W+w). m=c, n=d, k=h.
  gemm_gen<false, false, false, true><<<dim3(1, 1, kB * kW), 256>>>(
      q, 1, HC, 0, 1, kC,
      k, 1, HC, 0, 1, kC,
      s, 1, CC, 0, kC,
      nullptr, 1, nullptr, nullptr, 0.08838834764831845f, kH);

  // Pass 3: softmax denominators.
  softmax_sum<<<(int)((kB * CC) / 256), 256>>>(s, inv);

  // Pass 4: wn[b,w][c,e] = sum_d (e*inv)[d,c]*Wn[d,e] + bn[e]. m=c, n=e, k=d.
  gemm_gen<false, false, true, false><<<dim3(1, 1, kB * kW), 256>>>(
      s, 1, CC, 0, 1, kC,
      Wn, 1, 0, 0, 1, kC,
      wn, 1, CC, 0, kC,
      inv, kW, nullptr, bn, 1.f, kC);

  // Pass 5: m[b,w][h,c] = sum_e v[h,e]*wn[e,c]. m=h (grid.x=2), n=c, k=e.
  gemm_gen<true, false, false, false><<<dim3(2, 1, kB * kW), 256>>>(
      v, 1, HC, 0, kC, 1,
      wn, 1, CC, 0, 1, kC,
      q, 1, CH, 0, kH,
      nullptr, 1, nullptr, nullptr, 1.f, kC);

  // Pass 5.5: transpose m5 (B,W,C,H) -> m6 (B,H,C,W).
  trans_wh<<<dim3(kW / 32, kH / 32, kB * kC), dim3(32, 8)>>>(q, k);

  // Pass 6: out[b,h][w,o] = sum_c m6[c,w]*Wo[c,o] + bo[o]. m=w, n=o, k=c.
  gemm_gen<false, false, false, false><<<dim3(1, 1, kB * kH), 256>>>(
      k, 1, CW, 0, 1, kW,
      Wo, 1, 0, 0, 1, kC,
      out, 1, CW, 0, kW,
      nullptr, 1, nullptr, bo, 1.f, kC);
}